// round 1
// baseline (speedup 1.0000x reference)
#include <cuda_runtime.h>

// CMFMLoss: B=64, T=1024, D=256 (fixed by the problem).
// Algebraic identity used:
//   sum_{i!=j} cross_cos[i,j]
//     = (1/T) * [ sum_t <sum_i vn[i,t,:], sum_j an[j,t,:]>  -  sum_{b,t} cos_bt ]
// so everything is computable in a single streaming pass over f_v/f_a.

#define Bb 64
#define Tt 1024
#define Dd 256
#define EPSF 1e-8f

// Per-t (per-block) partials; reduced deterministically by pass 2.
__device__ float g_cross[Tt];
__device__ float g_cpos[Tt];
__device__ float g_cneg[Tt];

__global__ void __launch_bounds__(256, 4)
cmfm_pass1(const float* __restrict__ fv,
           const float* __restrict__ fa,
           const long long* __restrict__ labels)
{
    const int t    = blockIdx.x;        // one timestep per block
    const int lane = threadIdx.x & 31;
    const int w    = threadIdx.x >> 5;  // warp id, 0..7

    __shared__ float s_sv[8][Dd];   // per-warp partial sum of normalized v
    __shared__ float s_sa[8][Dd];   // per-warp partial sum of normalized a
    __shared__ float s_cp[8];
    __shared__ float s_cn[8];
    __shared__ float s_red[8];

    // Each warp handles 8 b-rows; each thread owns 8 d-values:
    // d in {4*lane+k, 128+4*lane+k} for k=0..3 (two float4 loads).
    float sv0 = 0.f, sv1 = 0.f, sv2 = 0.f, sv3 = 0.f;
    float sv4 = 0.f, sv5 = 0.f, sv6 = 0.f, sv7 = 0.f;
    float sa0 = 0.f, sa1 = 0.f, sa2 = 0.f, sa3 = 0.f;
    float sa4 = 0.f, sa5 = 0.f, sa6 = 0.f, sa7 = 0.f;
    float cp = 0.f, cn = 0.f;

    #pragma unroll
    for (int i = 0; i < 8; ++i) {
        const int b = w * 8 + i;
        const float4* __restrict__ vrow =
            reinterpret_cast<const float4*>(fv + ((size_t)b * Tt + t) * Dd);
        const float4* __restrict__ arow =
            reinterpret_cast<const float4*>(fa + ((size_t)b * Tt + t) * Dd);

        const float4 v0 = vrow[lane];
        const float4 v1 = vrow[lane + 32];
        const float4 a0 = arow[lane];
        const float4 a1 = arow[lane + 32];

        float nv2 = v0.x * v0.x;
        nv2 = fmaf(v0.y, v0.y, nv2); nv2 = fmaf(v0.z, v0.z, nv2);
        nv2 = fmaf(v0.w, v0.w, nv2); nv2 = fmaf(v1.x, v1.x, nv2);
        nv2 = fmaf(v1.y, v1.y, nv2); nv2 = fmaf(v1.z, v1.z, nv2);
        nv2 = fmaf(v1.w, v1.w, nv2);

        float na2 = a0.x * a0.x;
        na2 = fmaf(a0.y, a0.y, na2); na2 = fmaf(a0.z, a0.z, na2);
        na2 = fmaf(a0.w, a0.w, na2); na2 = fmaf(a1.x, a1.x, na2);
        na2 = fmaf(a1.y, a1.y, na2); na2 = fmaf(a1.z, a1.z, na2);
        na2 = fmaf(a1.w, a1.w, na2);

        float dt = v0.x * a0.x;
        dt = fmaf(v0.y, a0.y, dt); dt = fmaf(v0.z, a0.z, dt);
        dt = fmaf(v0.w, a0.w, dt); dt = fmaf(v1.x, a1.x, dt);
        dt = fmaf(v1.y, a1.y, dt); dt = fmaf(v1.z, a1.z, dt);
        dt = fmaf(v1.w, a1.w, dt);

        // Warp-wide butterfly reduce (all lanes end with full sums).
        #pragma unroll
        for (int off = 16; off > 0; off >>= 1) {
            nv2 += __shfl_xor_sync(0xffffffffu, nv2, off);
            na2 += __shfl_xor_sync(0xffffffffu, na2, off);
            dt  += __shfl_xor_sync(0xffffffffu, dt,  off);
        }

        const float inv_nv = 1.f / fmaxf(sqrtf(nv2), EPSF);
        const float inv_na = 1.f / fmaxf(sqrtf(na2), EPSF);

        sv0 = fmaf(v0.x, inv_nv, sv0); sv1 = fmaf(v0.y, inv_nv, sv1);
        sv2 = fmaf(v0.z, inv_nv, sv2); sv3 = fmaf(v0.w, inv_nv, sv3);
        sv4 = fmaf(v1.x, inv_nv, sv4); sv5 = fmaf(v1.y, inv_nv, sv5);
        sv6 = fmaf(v1.z, inv_nv, sv6); sv7 = fmaf(v1.w, inv_nv, sv7);

        sa0 = fmaf(a0.x, inv_na, sa0); sa1 = fmaf(a0.y, inv_na, sa1);
        sa2 = fmaf(a0.z, inv_na, sa2); sa3 = fmaf(a0.w, inv_na, sa3);
        sa4 = fmaf(a1.x, inv_na, sa4); sa5 = fmaf(a1.y, inv_na, sa5);
        sa6 = fmaf(a1.z, inv_na, sa6); sa7 = fmaf(a1.w, inv_na, sa7);

        if (lane == 0) {
            const float c = dt * inv_nv * inv_na;
            if (labels[b] == 0) cp += c; else cn += c;
        }
    }

    // Dump warp partials to smem (float4 stores, conflict-free).
    {
        float4* svp = reinterpret_cast<float4*>(s_sv[w]);
        float4* sap = reinterpret_cast<float4*>(s_sa[w]);
        svp[lane]      = make_float4(sv0, sv1, sv2, sv3);
        svp[lane + 32] = make_float4(sv4, sv5, sv6, sv7);
        sap[lane]      = make_float4(sa0, sa1, sa2, sa3);
        sap[lane + 32] = make_float4(sa4, sa5, sa6, sa7);
        if (lane == 0) { s_cp[w] = cp; s_cn[w] = cn; }
    }
    __syncthreads();

    // Combine 8 warp partials per d, then <Sv_t, Sa_t>.
    const int d = threadIdx.x;
    float tv = 0.f, ta = 0.f;
    #pragma unroll
    for (int ww = 0; ww < 8; ++ww) {
        tv += s_sv[ww][d];
        ta += s_sa[ww][d];
    }
    float prod = tv * ta;
    #pragma unroll
    for (int off = 16; off > 0; off >>= 1)
        prod += __shfl_xor_sync(0xffffffffu, prod, off);
    if (lane == 0) s_red[w] = prod;
    __syncthreads();

    if (threadIdx.x == 0) {
        float cr = 0.f, cpt = 0.f, cnt = 0.f;
        #pragma unroll
        for (int ww = 0; ww < 8; ++ww) {
            cr  += s_red[ww];
            cpt += s_cp[ww];
            cnt += s_cn[ww];
        }
        g_cross[t] = cr;
        g_cpos[t]  = cpt;
        g_cneg[t]  = cnt;
    }
}

__global__ void __launch_bounds__(256)
cmfm_pass2(const long long* __restrict__ labels, float* __restrict__ out)
{
    const int lane = threadIdx.x & 31;
    const int w    = threadIdx.x >> 5;
    __shared__ float r_cr[8], r_cp[8], r_cn[8];

    float cr = 0.f, cp = 0.f, cn = 0.f;
    for (int t = threadIdx.x; t < Tt; t += 256) {
        cr += g_cross[t];
        cp += g_cpos[t];
        cn += g_cneg[t];
    }
    #pragma unroll
    for (int off = 16; off > 0; off >>= 1) {
        cr += __shfl_xor_sync(0xffffffffu, cr, off);
        cp += __shfl_xor_sync(0xffffffffu, cp, off);
        cn += __shfl_xor_sync(0xffffffffu, cn, off);
    }
    if (lane == 0) { r_cr[w] = cr; r_cp[w] = cp; r_cn[w] = cn; }
    __syncthreads();

    if (threadIdx.x == 0) {
        float Cr = 0.f, Sp = 0.f, Sn = 0.f;
        #pragma unroll
        for (int ww = 0; ww < 8; ++ww) { Cr += r_cr[ww]; Sp += r_cp[ww]; Sn += r_cn[ww]; }

        int npos = 0;
        for (int b = 0; b < Bb; ++b) npos += (labels[b] == 0) ? 1 : 0;
        const float fpos = (float)npos;
        const float fneg = (float)(Bb - npos);

        // loss_pos = ALPHA * sum(d * pos) = 2 * (npos*T - Sp)
        const float loss_pos = 2.0f * (fpos * (float)Tt - Sp);
        // loss_neg = BETA * Sn + GAMMA * (Cross_all - diag) / T
        const float loss_neg = 2.0f * Sn + (Cr - (Sp + Sn)) / (float)Tt;

        const float cnt_pos = fpos * (float)Tt;
        const float cnt_neg = fneg * (float)Tt + (float)(Bb * (Bb - 1));

        float loss = 0.f;
        if (cnt_pos > 0.f) loss += loss_pos / fmaxf(cnt_pos, 1.0f);
        if (cnt_neg > 0.f) loss += loss_neg / fmaxf(cnt_neg, 1.0f);
        out[0] = loss;
    }
}

extern "C" void kernel_launch(void* const* d_in, const int* in_sizes, int n_in,
                              void* d_out, int out_size)
{
    const float*     fv     = (const float*)d_in[0];
    const float*     fa     = (const float*)d_in[1];
    const long long* labels = (const long long*)d_in[2];
    float*           out    = (float*)d_out;

    (void)in_sizes; (void)n_in; (void)out_size;

    cmfm_pass1<<<Tt, 256>>>(fv, fa, labels);
    cmfm_pass2<<<1, 256>>>(labels, out);
}

// round 2
// speedup vs baseline: 1.0010x; 1.0010x over previous
#include <cuda_runtime.h>

// CMFMLoss: B=64, T=1024, D=256. Single fused streaming kernel.
// Identity: sum_{i!=j} cross_cos[i,j]
//   = (1/T) * [ sum_t <sum_i vn[i,t,:], sum_j an[j,t,:]>  -  sum_{b,t} cos_bt ]

#define Bb 64
#define Tt 1024
#define Dd 256
#define NBLK 512          // 2 timesteps per block -> one balanced wave
#define EPSF 1e-8f

__device__ float    g_cr[NBLK];
__device__ float    g_cp[NBLK];
__device__ float    g_cn[NBLK];
__device__ unsigned g_done = 0;

__global__ void __launch_bounds__(256, 4)
cmfm_fused(const float* __restrict__ fv,
           const float* __restrict__ fa,
           const long long* __restrict__ labels,
           float* __restrict__ out)
{
    const int lane = threadIdx.x & 31;
    const int w    = threadIdx.x >> 5;   // warp 0..7

    __shared__ float s_sv[8][Dd];
    __shared__ float s_sa[8][Dd];
    __shared__ float s_cp[8];
    __shared__ float s_cn[8];
    __shared__ float s_red[8];
    __shared__ int   s_last;

    float blk_cr = 0.f, blk_cp = 0.f, blk_cn = 0.f;   // meaningful in thread 0

    #pragma unroll
    for (int tt = 0; tt < 2; ++tt) {
        const int t = blockIdx.x * 2 + tt;

        float sv0=0.f,sv1=0.f,sv2=0.f,sv3=0.f,sv4=0.f,sv5=0.f,sv6=0.f,sv7=0.f;
        float sa0=0.f,sa1=0.f,sa2=0.f,sa3=0.f,sa4=0.f,sa5=0.f,sa6=0.f,sa7=0.f;
        float cp = 0.f, cn = 0.f;

        #pragma unroll
        for (int i = 0; i < 8; ++i) {
            const int b = w * 8 + i;
            const float4* __restrict__ vrow =
                reinterpret_cast<const float4*>(fv + ((size_t)b * Tt + t) * Dd);
            const float4* __restrict__ arow =
                reinterpret_cast<const float4*>(fa + ((size_t)b * Tt + t) * Dd);

            const float4 v0 = vrow[lane];
            const float4 v1 = vrow[lane + 32];
            const float4 a0 = arow[lane];
            const float4 a1 = arow[lane + 32];

            float nv2 = v0.x*v0.x;
            nv2 = fmaf(v0.y,v0.y,nv2); nv2 = fmaf(v0.z,v0.z,nv2);
            nv2 = fmaf(v0.w,v0.w,nv2); nv2 = fmaf(v1.x,v1.x,nv2);
            nv2 = fmaf(v1.y,v1.y,nv2); nv2 = fmaf(v1.z,v1.z,nv2);
            nv2 = fmaf(v1.w,v1.w,nv2);

            float na2 = a0.x*a0.x;
            na2 = fmaf(a0.y,a0.y,na2); na2 = fmaf(a0.z,a0.z,na2);
            na2 = fmaf(a0.w,a0.w,na2); na2 = fmaf(a1.x,a1.x,na2);
            na2 = fmaf(a1.y,a1.y,na2); na2 = fmaf(a1.z,a1.z,na2);
            na2 = fmaf(a1.w,a1.w,na2);

            float dt = v0.x*a0.x;
            dt = fmaf(v0.y,a0.y,dt); dt = fmaf(v0.z,a0.z,dt);
            dt = fmaf(v0.w,a0.w,dt); dt = fmaf(v1.x,a1.x,dt);
            dt = fmaf(v1.y,a1.y,dt); dt = fmaf(v1.z,a1.z,dt);
            dt = fmaf(v1.w,a1.w,dt);

            #pragma unroll
            for (int off = 16; off > 0; off >>= 1) {
                nv2 += __shfl_xor_sync(0xffffffffu, nv2, off);
                na2 += __shfl_xor_sync(0xffffffffu, na2, off);
                dt  += __shfl_xor_sync(0xffffffffu, dt,  off);
            }

            const float inv_nv = 1.f / fmaxf(sqrtf(nv2), EPSF);
            const float inv_na = 1.f / fmaxf(sqrtf(na2), EPSF);

            sv0 = fmaf(v0.x,inv_nv,sv0); sv1 = fmaf(v0.y,inv_nv,sv1);
            sv2 = fmaf(v0.z,inv_nv,sv2); sv3 = fmaf(v0.w,inv_nv,sv3);
            sv4 = fmaf(v1.x,inv_nv,sv4); sv5 = fmaf(v1.y,inv_nv,sv5);
            sv6 = fmaf(v1.z,inv_nv,sv6); sv7 = fmaf(v1.w,inv_nv,sv7);

            sa0 = fmaf(a0.x,inv_na,sa0); sa1 = fmaf(a0.y,inv_na,sa1);
            sa2 = fmaf(a0.z,inv_na,sa2); sa3 = fmaf(a0.w,inv_na,sa3);
            sa4 = fmaf(a1.x,inv_na,sa4); sa5 = fmaf(a1.y,inv_na,sa5);
            sa6 = fmaf(a1.z,inv_na,sa6); sa7 = fmaf(a1.w,inv_na,sa7);

            if (lane == 0) {
                const float c = dt * inv_nv * inv_na;
                if (labels[b] == 0) cp += c; else cn += c;
            }
        }

        if (tt == 1) __syncthreads();   // protect smem reuse from prior iter's reads

        {
            float4* svp = reinterpret_cast<float4*>(s_sv[w]);
            float4* sap = reinterpret_cast<float4*>(s_sa[w]);
            svp[lane]      = make_float4(sv0, sv1, sv2, sv3);
            svp[lane + 32] = make_float4(sv4, sv5, sv6, sv7);
            sap[lane]      = make_float4(sa0, sa1, sa2, sa3);
            sap[lane + 32] = make_float4(sa4, sa5, sa6, sa7);
            if (lane == 0) { s_cp[w] = cp; s_cn[w] = cn; }
        }
        __syncthreads();

        // <Sv_t, Sa_t> across the 8 warp partials.
        const int d = threadIdx.x;
        float tv = 0.f, ta = 0.f;
        #pragma unroll
        for (int ww = 0; ww < 8; ++ww) { tv += s_sv[ww][d]; ta += s_sa[ww][d]; }
        float prod = tv * ta;
        #pragma unroll
        for (int off = 16; off > 0; off >>= 1)
            prod += __shfl_xor_sync(0xffffffffu, prod, off);
        if (lane == 0) s_red[w] = prod;
        __syncthreads();

        if (threadIdx.x == 0) {
            #pragma unroll
            for (int ww = 0; ww < 8; ++ww) {
                blk_cr += s_red[ww];
                blk_cp += s_cp[ww];
                blk_cn += s_cn[ww];
            }
        }
    }

    // Publish block partials; last block to arrive performs the final reduce.
    if (threadIdx.x == 0) {
        g_cr[blockIdx.x] = blk_cr;
        g_cp[blockIdx.x] = blk_cp;
        g_cn[blockIdx.x] = blk_cn;
        __threadfence();
        const unsigned old = atomicAdd(&g_done, 1u);
        s_last = (old == NBLK - 1) ? 1 : 0;
    }
    __syncthreads();
    if (!s_last) return;

    // ---- Final reduction (one block, deterministic order) ----
    {
        float cr = 0.f, cp = 0.f, cn = 0.f;
        #pragma unroll
        for (int k = 0; k < NBLK / 256; ++k) {
            const int i = threadIdx.x + k * 256;
            cr += g_cr[i]; cp += g_cp[i]; cn += g_cn[i];
        }
        #pragma unroll
        for (int off = 16; off > 0; off >>= 1) {
            cr += __shfl_xor_sync(0xffffffffu, cr, off);
            cp += __shfl_xor_sync(0xffffffffu, cp, off);
            cn += __shfl_xor_sync(0xffffffffu, cn, off);
        }
        if (lane == 0) { s_red[w] = cr; s_cp[w] = cp; s_cn[w] = cn; }
        __syncthreads();

        if (threadIdx.x == 0) {
            float Cr = 0.f, Sp = 0.f, Sn = 0.f;
            #pragma unroll
            for (int ww = 0; ww < 8; ++ww) { Cr += s_red[ww]; Sp += s_cp[ww]; Sn += s_cn[ww]; }

            int npos = 0;
            for (int b = 0; b < Bb; ++b) npos += (labels[b] == 0) ? 1 : 0;
            const float fpos = (float)npos;
            const float fneg = (float)(Bb - npos);

            const float loss_pos = 2.0f * (fpos * (float)Tt - Sp);
            const float loss_neg = 2.0f * Sn + (Cr - (Sp + Sn)) / (float)Tt;

            const float cnt_pos = fpos * (float)Tt;
            const float cnt_neg = fneg * (float)Tt + (float)(Bb * (Bb - 1));

            float loss = 0.f;
            if (cnt_pos > 0.f) loss += loss_pos / fmaxf(cnt_pos, 1.0f);
            if (cnt_neg > 0.f) loss += loss_neg / fmaxf(cnt_neg, 1.0f);
            out[0] = loss;

            g_done = 0;   // self-reset for next (graph-replayed) call
        }
    }
}

extern "C" void kernel_launch(void* const* d_in, const int* in_sizes, int n_in,
                              void* d_out, int out_size)
{
    const float*     fv     = (const float*)d_in[0];
    const float*     fa     = (const float*)d_in[1];
    const long long* labels = (const long long*)d_in[2];
    float*           out    = (float*)d_out;

    (void)in_sizes; (void)n_in; (void)out_size;

    cmfm_fused<<<NBLK, 256>>>(fv, fa, labels, out);
}

// round 4
// speedup vs baseline: 1.0620x; 1.0609x over previous
#include <cuda_runtime.h>

// CMFMLoss: B=64, T=1024, D=256. Single fused streaming kernel.
// Identity: sum_{i!=j} cross_cos[i,j]
//   = (1/T) * [ sum_t <sum_i vn[i,t,:], sum_j an[j,t,:]>  -  sum_{b,t} cos_bt ]
// Per-lane trick: cos_bt = sum_lane(dt_part) * invV * invA, so the label-weighted
// cosine sums accumulate per-lane (no per-row dt reduction needed).

#define Bb 64
#define Tt 1024
#define Dd 256
#define NBLK 1024          // one timestep per block (known-good shape)
#define EPS2 1e-16f

__device__ float    g_cr[NBLK];
__device__ float    g_cp[NBLK];
__device__ float    g_cn[NBLK];
__device__ unsigned g_done = 0;

__device__ __forceinline__ float dot8(const float4& x0, const float4& x1,
                                      const float4& y0, const float4& y1) {
    float s = x0.x * y0.x;
    s = fmaf(x0.y, y0.y, s); s = fmaf(x0.z, y0.z, s); s = fmaf(x0.w, y0.w, s);
    s = fmaf(x1.x, y1.x, s); s = fmaf(x1.y, y1.y, s);
    s = fmaf(x1.z, y1.z, s); s = fmaf(x1.w, y1.w, s);
    return s;
}

__device__ __forceinline__ float bfly_add(float v) {
    #pragma unroll
    for (int off = 16; off > 0; off >>= 1)
        v += __shfl_xor_sync(0xffffffffu, v, off);
    return v;
}

__global__ void __launch_bounds__(256, 4)
cmfm_fused(const float* __restrict__ fv,
           const float* __restrict__ fa,
           const long long* __restrict__ labels,
           float* __restrict__ out)
{
    const int t    = blockIdx.x;
    const int lane = threadIdx.x & 31;
    const int w    = threadIdx.x >> 5;   // warp 0..7

    __shared__ float s_sv[8][Dd];
    __shared__ float s_sa[8][Dd];
    __shared__ float s_cp[8];
    __shared__ float s_cn[8];
    __shared__ float s_red[8];
    __shared__ int   s_last;

    float sv0=0.f,sv1=0.f,sv2=0.f,sv3=0.f,sv4=0.f,sv5=0.f,sv6=0.f,sv7=0.f;
    float sa0=0.f,sa1=0.f,sa2=0.f,sa3=0.f,sa4=0.f,sa5=0.f,sa6=0.f,sa7=0.f;
    float cp = 0.f, cn = 0.f;   // per-lane partial cosine sums

    // Two b-rows per iteration: 8 LDG.128 in flight, overlapped reduce chains.
    #pragma unroll
    for (int i = 0; i < 8; i += 2) {
        const int bA = w * 8 + i;
        const int bB = bA + 1;

        const float4* __restrict__ vrA =
            reinterpret_cast<const float4*>(fv + ((size_t)bA * Tt + t) * Dd);
        const float4* __restrict__ arA =
            reinterpret_cast<const float4*>(fa + ((size_t)bA * Tt + t) * Dd);
        const float4* __restrict__ vrB =
            reinterpret_cast<const float4*>(fv + ((size_t)bB * Tt + t) * Dd);
        const float4* __restrict__ arB =
            reinterpret_cast<const float4*>(fa + ((size_t)bB * Tt + t) * Dd);

        const float4 vA0 = vrA[lane];
        const float4 vA1 = vrA[lane + 32];
        const float4 aA0 = arA[lane];
        const float4 aA1 = arA[lane + 32];
        const float4 vB0 = vrB[lane];
        const float4 vB1 = vrB[lane + 32];
        const float4 aB0 = arB[lane];
        const float4 aB1 = arB[lane + 32];

        float nvA = dot8(vA0, vA1, vA0, vA1);
        float naA = dot8(aA0, aA1, aA0, aA1);
        float nvB = dot8(vB0, vB1, vB0, vB1);
        float naB = dot8(aB0, aB1, aB0, aB1);
        const float dtA = dot8(vA0, vA1, aA0, aA1);   // per-lane partial, NOT reduced
        const float dtB = dot8(vB0, vB1, aB0, aB1);

        // Interleaved butterflies (4 chains overlap).
        #pragma unroll
        for (int off = 16; off > 0; off >>= 1) {
            nvA += __shfl_xor_sync(0xffffffffu, nvA, off);
            naA += __shfl_xor_sync(0xffffffffu, naA, off);
            nvB += __shfl_xor_sync(0xffffffffu, nvB, off);
            naB += __shfl_xor_sync(0xffffffffu, naB, off);
        }

        const float invVA = rsqrtf(fmaxf(nvA, EPS2));
        const float invAA = rsqrtf(fmaxf(naA, EPS2));
        const float invVB = rsqrtf(fmaxf(nvB, EPS2));
        const float invAB = rsqrtf(fmaxf(naB, EPS2));

        sv0 = fmaf(vA0.x, invVA, sv0); sv1 = fmaf(vA0.y, invVA, sv1);
        sv2 = fmaf(vA0.z, invVA, sv2); sv3 = fmaf(vA0.w, invVA, sv3);
        sv4 = fmaf(vA1.x, invVA, sv4); sv5 = fmaf(vA1.y, invVA, sv5);
        sv6 = fmaf(vA1.z, invVA, sv6); sv7 = fmaf(vA1.w, invVA, sv7);
        sa0 = fmaf(aA0.x, invAA, sa0); sa1 = fmaf(aA0.y, invAA, sa1);
        sa2 = fmaf(aA0.z, invAA, sa2); sa3 = fmaf(aA0.w, invAA, sa3);
        sa4 = fmaf(aA1.x, invAA, sa4); sa5 = fmaf(aA1.y, invAA, sa5);
        sa6 = fmaf(aA1.z, invAA, sa6); sa7 = fmaf(aA1.w, invAA, sa7);

        sv0 = fmaf(vB0.x, invVB, sv0); sv1 = fmaf(vB0.y, invVB, sv1);
        sv2 = fmaf(vB0.z, invVB, sv2); sv3 = fmaf(vB0.w, invVB, sv3);
        sv4 = fmaf(vB1.x, invVB, sv4); sv5 = fmaf(vB1.y, invVB, sv5);
        sv6 = fmaf(vB1.z, invVB, sv6); sv7 = fmaf(vB1.w, invVB, sv7);
        sa0 = fmaf(aB0.x, invAB, sa0); sa1 = fmaf(aB0.y, invAB, sa1);
        sa2 = fmaf(aB0.z, invAB, sa2); sa3 = fmaf(aB0.w, invAB, sa3);
        sa4 = fmaf(aB1.x, invAB, sa4); sa5 = fmaf(aB1.y, invAB, sa5);
        sa6 = fmaf(aB1.z, invAB, sa6); sa7 = fmaf(aB1.w, invAB, sa7);

        // Per-lane label-weighted cosine partials.
        const float csA = dtA * (invVA * invAA);
        const float csB = dtB * (invVB * invAB);
        if (labels[bA] == 0) cp += csA; else cn += csA;
        if (labels[bB] == 0) cp += csB; else cn += csB;
    }

    // Reduce per-lane cp/cn once per warp.
    cp = bfly_add(cp);
    cn = bfly_add(cn);

    {
        float4* svp = reinterpret_cast<float4*>(s_sv[w]);
        float4* sap = reinterpret_cast<float4*>(s_sa[w]);
        svp[lane]      = make_float4(sv0, sv1, sv2, sv3);
        svp[lane + 32] = make_float4(sv4, sv5, sv6, sv7);
        sap[lane]      = make_float4(sa0, sa1, sa2, sa3);
        sap[lane + 32] = make_float4(sa4, sa5, sa6, sa7);
        if (lane == 0) { s_cp[w] = cp; s_cn[w] = cn; }
    }
    __syncthreads();

    // <Sv_t, Sa_t> across the 8 warp partials.
    const int d = threadIdx.x;
    float tv = 0.f, ta = 0.f;
    #pragma unroll
    for (int ww = 0; ww < 8; ++ww) { tv += s_sv[ww][d]; ta += s_sa[ww][d]; }
    float prod = bfly_add(tv * ta);
    if (lane == 0) s_red[w] = prod;
    __syncthreads();

    // Publish block partials; last block performs the final reduce.
    if (threadIdx.x == 0) {
        float cr = 0.f, cpt = 0.f, cnt = 0.f;
        #pragma unroll
        for (int ww = 0; ww < 8; ++ww) {
            cr  += s_red[ww];
            cpt += s_cp[ww];
            cnt += s_cn[ww];
        }
        g_cr[t] = cr;
        g_cp[t] = cpt;
        g_cn[t] = cnt;
        __threadfence();
        const unsigned old = atomicAdd(&g_done, 1u);
        s_last = (old == NBLK - 1) ? 1 : 0;
    }
    __syncthreads();
    if (!s_last) return;

    // ---- Final reduction (one block, deterministic order) ----
    {
        float cr = 0.f, cpr = 0.f, cnr = 0.f;
        #pragma unroll
        for (int k = 0; k < NBLK / 256; ++k) {
            const int i = threadIdx.x + k * 256;
            cr += g_cr[i]; cpr += g_cp[i]; cnr += g_cn[i];
        }
        cr  = bfly_add(cr);
        cpr = bfly_add(cpr);
        cnr = bfly_add(cnr);
        if (lane == 0) { s_red[w] = cr; s_cp[w] = cpr; s_cn[w] = cnr; }
        __syncthreads();

        if (threadIdx.x == 0) {
            float Cr = 0.f, Sp = 0.f, Sn = 0.f;
            #pragma unroll
            for (int ww = 0; ww < 8; ++ww) { Cr += s_red[ww]; Sp += s_cp[ww]; Sn += s_cn[ww]; }

            int npos = 0;
            for (int b = 0; b < Bb; ++b) npos += (labels[b] == 0) ? 1 : 0;
            const float fpos = (float)npos;
            const float fneg = (float)(Bb - npos);

            const float loss_pos = 2.0f * (fpos * (float)Tt - Sp);
            const float loss_neg = 2.0f * Sn + (Cr - (Sp + Sn)) / (float)Tt;

            const float cnt_pos = fpos * (float)Tt;
            const float cnt_neg = fneg * (float)Tt + (float)(Bb * (Bb - 1));

            float loss = 0.f;
            if (cnt_pos > 0.f) loss += loss_pos / fmaxf(cnt_pos, 1.0f);
            if (cnt_neg > 0.f) loss += loss_neg / fmaxf(cnt_neg, 1.0f);
            out[0] = loss;

            g_done = 0;   // self-reset for next (graph-replayed) call
        }
    }
}

extern "C" void kernel_launch(void* const* d_in, const int* in_sizes, int n_in,
                              void* d_out, int out_size)
{
    const float*     fv     = (const float*)d_in[0];
    const float*     fa     = (const float*)d_in[1];
    const long long* labels = (const long long*)d_in[2];
    float*           out    = (float*)d_out;

    (void)in_sizes; (void)n_in; (void)out_size;

    cmfm_fused<<<NBLK, 256>>>(fv, fa, labels, out);
}